// round 4
// baseline (speedup 1.0000x reference)
#include <cuda_runtime.h>

#define NB 4
#define NT 4096
#define ND 64
#define LDT 132   // padded leading dim for K-major [64][128] tiles
#define LDX 68    // padded leading dim for natural [128][64] tiles

// Scratch (device globals: no allocation allowed)
__device__ float g_encT[NB*ND*NT];  // [b][d][t]
__device__ float g_xT[NB*ND*NT];    // [b][d][t]
__device__ float g_m[NB*NT];
__device__ float g_rz[NB*NT];

// ---------------------------------------------------------------------------
// Kernel 1: per-row MLP  enc = tanh(softmax(x W1 + b1) W2 + b2)
// Also writes xT and encT (d-major) for the GEMM kernels.
// One warp per row, 8 rows per 256-thread block.
// ---------------------------------------------------------------------------
__global__ void __launch_bounds__(256) mlp_kernel(
    const float* __restrict__ x, const float* __restrict__ W1,
    const float* __restrict__ b1, const float* __restrict__ W2,
    const float* __restrict__ b2)
{
    __shared__ float sW1[64*64];
    __shared__ float sW2[64*64];
    __shared__ float sbuf[8][64];
    int tid = threadIdx.x;
    #pragma unroll
    for (int i = tid*4; i < 4096; i += 1024) {
        *(float4*)&sW1[i] = *(const float4*)&W1[i];
        *(float4*)&sW2[i] = *(const float4*)&W2[i];
    }
    int w = tid >> 5, lane = tid & 31;
    int row = blockIdx.x*8 + w;            // 0..16383
    int b = row >> 12, t = row & 4095;
    const float* xr = x + (size_t)row*64;
    float x0 = xr[lane], x1 = xr[lane+32];
    g_xT[((size_t)(b*64+lane   ))*4096 + t] = x0;
    g_xT[((size_t)(b*64+lane+32))*4096 + t] = x1;
    __syncthreads();                        // W1/W2 ready
    sbuf[w][lane] = x0; sbuf[w][lane+32] = x1;
    __syncwarp();
    float a0 = b1[lane], a1 = b1[lane+32];
    #pragma unroll
    for (int d = 0; d < 64; d++) {
        float xv = sbuf[w][d];
        a0 = fmaf(xv, sW1[d*64+lane   ], a0);
        a1 = fmaf(xv, sW1[d*64+lane+32], a1);
    }
    float mm = fmaxf(a0, a1);
    #pragma unroll
    for (int o = 16; o > 0; o >>= 1) mm = fmaxf(mm, __shfl_xor_sync(0xffffffffu, mm, o));
    float e0 = __expf(a0 - mm), e1 = __expf(a1 - mm);
    float ss = e0 + e1;
    #pragma unroll
    for (int o = 16; o > 0; o >>= 1) ss += __shfl_xor_sync(0xffffffffu, ss, o);
    float rs = 1.0f/ss;
    __syncwarp();
    sbuf[w][lane] = e0*rs; sbuf[w][lane+32] = e1*rs;
    __syncwarp();
    float c0 = b2[lane], c1 = b2[lane+32];
    #pragma unroll
    for (int d = 0; d < 64; d++) {
        float hv = sbuf[w][d];
        c0 = fmaf(hv, sW2[d*64+lane   ], c0);
        c1 = fmaf(hv, sW2[d*64+lane+32], c1);
    }
    g_encT[((size_t)(b*64+lane   ))*4096 + t] = tanhf(c0);
    g_encT[((size_t)(b*64+lane+32))*4096 + t] = tanhf(c1);
}

// Load a K-major [64][128] tile (padded to LDT) from a d-major global array.
__device__ __forceinline__ void load_tileT(float* dst, const float* __restrict__ src,
                                           int col0, int tid)
{
    #pragma unroll
    for (int it = tid; it < 64*32; it += 256) {
        int d = it >> 5, c4 = it & 31;
        float4 v = *(const float4*)&src[(size_t)d*4096 + col0 + c4*4];
        *(float4*)&dst[d*LDT + c4*4] = v;
    }
}

// ---------------------------------------------------------------------------
// Kernel 2: per-row-j softmax stats.  s_ji = x_j . enc_i  (i = all 4096)
// Block = (batch b, j-tile of 128).  128x128x64 GEMM, 8x8 microtile/thread.
// Online max/sum over i, reduced across the 16 threads sharing each j-row.
// ---------------------------------------------------------------------------
__global__ void __launch_bounds__(256,1) stats_kernel()
{
    extern __shared__ float smem[];
    float* sA = smem;             // xT   j-tile, [64][LDT]
    float* sB = smem + 64*LDT;    // encT i-tile, [64][LDT]
    int tid = threadIdx.x;
    int b  = blockIdx.x >> 5;
    int j0 = (blockIdx.x & 31) * 128;
    const float* xTb = g_xT   + (size_t)b*64*4096;
    const float* eTb = g_encT + (size_t)b*64*4096;
    load_tileT(sA, xTb, j0, tid);
    int ty = tid >> 4, tx = tid & 15;
    float m[8], Z[8];
    #pragma unroll
    for (int r = 0; r < 8; r++) { m[r] = -1e30f; Z[r] = 0.0f; }

    for (int itile = 0; itile < 32; ++itile) {
        __syncthreads();
        load_tileT(sB, eTb, itile*128, tid);
        __syncthreads();
        float c[8][8];
        #pragma unroll
        for (int r = 0; r < 8; r++)
            #pragma unroll
            for (int cc = 0; cc < 8; cc++) c[r][cc] = 0.0f;
        #pragma unroll 8
        for (int k = 0; k < 64; k++) {
            float a[8], bb[8];
            *(float4*)&a[0]  = *(const float4*)&sA[k*LDT + ty*8];
            *(float4*)&a[4]  = *(const float4*)&sA[k*LDT + ty*8 + 4];
            *(float4*)&bb[0] = *(const float4*)&sB[k*LDT + tx*8];
            *(float4*)&bb[4] = *(const float4*)&sB[k*LDT + tx*8 + 4];
            #pragma unroll
            for (int r = 0; r < 8; r++)
                #pragma unroll
                for (int cc = 0; cc < 8; cc++)
                    c[r][cc] = fmaf(a[r], bb[cc], c[r][cc]);
        }
        #pragma unroll
        for (int r = 0; r < 8; r++) {
            float tm = c[r][0];
            #pragma unroll
            for (int cc = 1; cc < 8; cc++) tm = fmaxf(tm, c[r][cc]);
            #pragma unroll
            for (int o = 1; o < 16; o <<= 1) tm = fmaxf(tm, __shfl_xor_sync(0xffffffffu, tm, o));
            float nm = fmaxf(m[r], tm);
            float ps = 0.0f;
            #pragma unroll
            for (int cc = 0; cc < 8; cc++) ps += __expf(c[r][cc] - nm);
            #pragma unroll
            for (int o = 1; o < 16; o <<= 1) ps += __shfl_xor_sync(0xffffffffu, ps, o);
            Z[r] = Z[r]*__expf(m[r] - nm) + ps;
            m[r] = nm;
        }
    }
    if (tx == 0) {
        #pragma unroll
        for (int r = 0; r < 8; r++) {
            int j = j0 + ty*8 + r;
            g_m [b*4096 + j] = m[r];
            g_rz[b*4096 + j] = 1.0f/Z[r];
        }
    }
}

// ---------------------------------------------------------------------------
// Kernel 3: out[i,d] = sum_j exp(x_j.enc_i - m_j) * rz_j * x[j,d]
// Block = (batch b, i-tile of 128).  Loops j-tiles: GEMM1 (scores) ->
// exp/scale -> stage P[j][i] in smem -> GEMM2 accumulate 128x64 out-tile.
// ---------------------------------------------------------------------------
__global__ void __launch_bounds__(256,1) out_kernel(const float* __restrict__ x,
                                                    float* __restrict__ out)
{
    extern __shared__ float smem[];
    float* sBi = smem;               // encT i-tile  [64][LDT] (fixed per block)
    float* sA  = sBi + 64*LDT;       // xT   j-tile  [64][LDT]
    float* sXj = sA  + 64*LDT;       // x natural    [128][LDX]
    float* sP  = sXj + 128*LDX;      // P            [128][LDT]
    float* sm_ = sP  + 128*LDT;      // m_j          [128]
    float* sz_ = sm_ + 128;          // rz_j         [128]
    int tid = threadIdx.x;
    int b  = blockIdx.x >> 5;
    int i0 = (blockIdx.x & 31) * 128;
    const float* xTb = g_xT   + (size_t)b*64*4096;
    const float* eTb = g_encT + (size_t)b*64*4096;
    const float* xb  = x + (size_t)b*4096*64;
    load_tileT(sBi, eTb, i0, tid);
    int ty = tid >> 4, tx = tid & 15;
    float o[8][4];
    #pragma unroll
    for (int r = 0; r < 8; r++)
        #pragma unroll
        for (int cc = 0; cc < 4; cc++) o[r][cc] = 0.0f;

    for (int jt = 0; jt < 32; ++jt) {
        int j0 = jt*128;
        __syncthreads();                                   // prev readers done
        load_tileT(sA, xTb, j0, tid);
        #pragma unroll
        for (int it = tid; it < 128*16; it += 256) {       // x j-tile, natural layout
            int j = it >> 4, c4 = it & 15;
            float4 v = *(const float4*)&xb[(size_t)(j0+j)*64 + c4*4];
            *(float4*)&sXj[j*LDX + c4*4] = v;
        }
        if (tid < 128) sm_[tid]       = g_m [b*4096 + j0 + tid];
        else           sz_[tid - 128] = g_rz[b*4096 + j0 + tid - 128];
        __syncthreads();

        // GEMM1: c[r=j][cc=i]
        float c[8][8];
        #pragma unroll
        for (int r = 0; r < 8; r++)
            #pragma unroll
            for (int cc = 0; cc < 8; cc++) c[r][cc] = 0.0f;
        #pragma unroll 8
        for (int k = 0; k < 64; k++) {
            float a[8], bb[8];
            *(float4*)&a[0]  = *(const float4*)&sA [k*LDT + ty*8];
            *(float4*)&a[4]  = *(const float4*)&sA [k*LDT + ty*8 + 4];
            *(float4*)&bb[0] = *(const float4*)&sBi[k*LDT + tx*8];
            *(float4*)&bb[4] = *(const float4*)&sBi[k*LDT + tx*8 + 4];
            #pragma unroll
            for (int r = 0; r < 8; r++)
                #pragma unroll
                for (int cc = 0; cc < 8; cc++)
                    c[r][cc] = fmaf(a[r], bb[cc], c[r][cc]);
        }
        // p = exp(s - m_j) * rz_j  -> stage into sP[j][i]
        #pragma unroll
        for (int r = 0; r < 8; r++) {
            float mj = sm_[ty*8 + r], rz = sz_[ty*8 + r];
            float4 p0, p1;
            p0.x = __expf(c[r][0]-mj)*rz; p0.y = __expf(c[r][1]-mj)*rz;
            p0.z = __expf(c[r][2]-mj)*rz; p0.w = __expf(c[r][3]-mj)*rz;
            p1.x = __expf(c[r][4]-mj)*rz; p1.y = __expf(c[r][5]-mj)*rz;
            p1.z = __expf(c[r][6]-mj)*rz; p1.w = __expf(c[r][7]-mj)*rz;
            *(float4*)&sP[(ty*8+r)*LDT + tx*8    ] = p0;
            *(float4*)&sP[(ty*8+r)*LDT + tx*8 + 4] = p1;
        }
        __syncthreads();

        // GEMM2: out[i=ty*8+r][d=tx*4+cc] += sum_j P[j][i] * x[j][d]
        #pragma unroll 8
        for (int k = 0; k < 128; k++) {
            float a[8], bb[4];
            *(float4*)&a[0]  = *(const float4*)&sP [k*LDT + ty*8];
            *(float4*)&a[4]  = *(const float4*)&sP [k*LDT + ty*8 + 4];
            *(float4*)&bb[0] = *(const float4*)&sXj[k*LDX + tx*4];
            #pragma unroll
            for (int r = 0; r < 8; r++)
                #pragma unroll
                for (int cc = 0; cc < 4; cc++)
                    o[r][cc] = fmaf(a[r], bb[cc], o[r][cc]);
        }
    }
    #pragma unroll
    for (int r = 0; r < 8; r++) {
        size_t base = ((size_t)(b*4096 + i0 + ty*8 + r))*64 + tx*4;
        *(float4*)&out[base] = make_float4(o[r][0], o[r][1], o[r][2], o[r][3]);
    }
}

// ---------------------------------------------------------------------------
extern "C" void kernel_launch(void* const* d_in, const int* in_sizes, int n_in,
                              void* d_out, int out_size)
{
    (void)in_sizes; (void)n_in; (void)out_size;
    const float* x  = (const float*)d_in[0];
    const float* W1 = (const float*)d_in[1];
    const float* b1 = (const float*)d_in[2];
    const float* W2 = (const float*)d_in[3];
    const float* b2 = (const float*)d_in[4];
    float* out = (float*)d_out;

    const int SMEM2 = (2*64*LDT) * (int)sizeof(float);                         // 67584 B
    const int SMEM3 = (2*64*LDT + 128*LDX + 128*LDT + 256) * (int)sizeof(float); // 171008 B
    cudaFuncSetAttribute(stats_kernel, cudaFuncAttributeMaxDynamicSharedMemorySize, SMEM2);
    cudaFuncSetAttribute(out_kernel,   cudaFuncAttributeMaxDynamicSharedMemorySize, SMEM3);

    mlp_kernel<<<2048, 256>>>(x, W1, b1, W2, b2);
    stats_kernel<<<128, 256, SMEM2>>>();
    out_kernel<<<128, 256, SMEM3>>>(x, out);
}